// round 4
// baseline (speedup 1.0000x reference)
#include <cuda_runtime.h>
#include <cuda_bf16.h>

// Problem constants (max sizes for static scratch; actual sizes derived from in_sizes)
#define CDIM   256
#define NV_MAX 20000
#define ME_MAX 4000
#define NNZ_MAX 160000

// -------------------- static device scratch (no allocations allowed) --------------------
// NOTE: Xp (the projected features) lives in d_out, not a static: the GEMM writes it
// there, edge_gather reads it, and vertex_gather overwrites d_out afterwards (reading
// only d_Xe). This keeps statics small.
__device__ float d_Xe[ME_MAX * CDIM];      // per-edge aggregated (already scaled)
__device__ int   d_cntE[ME_MAX];
__device__ int   d_cntV[NV_MAX];
__device__ int   d_offE[ME_MAX + 1];
__device__ int   d_offV[NV_MAX + 1];
__device__ int   d_curE[ME_MAX];
__device__ int   d_curV[NV_MAX];
__device__ int   d_csrE_v[NNZ_MAX];        // vertices grouped by edge
__device__ int   d_csrV_e[NNZ_MAX];        // edges grouped by vertex
__device__ float d_degV[NV_MAX];           // rsqrt(distinct-edge count) or 1
__device__ float d_sE[ME_MAX];             // rsqrt(distinct-vertex cnt) / (count + 1e-8)

// -------------------- zero counters --------------------
__global__ void zero_kernel(int Me, int Nv)
{
    int total = 2 * (Me + Nv);
    for (int i = blockIdx.x * blockDim.x + threadIdx.x; i < total;
         i += gridDim.x * blockDim.x) {
        int j = i;
        if (j < Me) { d_cntE[j] = 0; continue; } j -= Me;
        if (j < Me) { d_curE[j] = 0; continue; } j -= Me;
        if (j < Nv) { d_cntV[j] = 0; continue; } j -= Nv;
        d_curV[j] = 0;
    }
}

// -------------------- raw counts --------------------
__global__ void count_kernel(const int* __restrict__ vertex, const int* __restrict__ edges,
                             int nnz)
{
    int k = blockIdx.x * blockDim.x + threadIdx.x;
    if (k >= nnz) return;
    atomicAdd(&d_cntE[edges[k]], 1);
    atomicAdd(&d_cntV[vertex[k]], 1);
}

// -------------------- single-block exclusive scan (L <= 20480), scalar accumulators only ----
__global__ void scan_kernel(int which, int L)   // 0: cntE->offE, 1: cntV->offV
{
    const int* __restrict__ in = which ? d_cntV : d_cntE;
    int* __restrict__ out      = which ? d_offV : d_offE;
    __shared__ int sums[1024];
    int tid = threadIdx.x;
    int per = (L + 1023) >> 10;
    int base = tid * per;
    int s = 0;
    for (int i = 0; i < per; i++) {
        int idx = base + i;
        if (idx < L) s += in[idx];
    }
    sums[tid] = s;
    __syncthreads();
    for (int off = 1; off < 1024; off <<= 1) {
        int t = (tid >= off) ? sums[tid - off] : 0;
        __syncthreads();
        sums[tid] += t;
        __syncthreads();
    }
    int run = (tid == 0) ? 0 : sums[tid - 1];
    for (int i = 0; i < per; i++) {
        int idx = base + i;
        if (idx < L) { out[idx] = run; run += in[idx]; }
    }
    if (tid == 1023) out[L] = sums[1023];
}

// -------------------- CSR fill --------------------
__global__ void fill_kernel(const int* __restrict__ vertex, const int* __restrict__ edges, int nnz)
{
    int k = blockIdx.x * blockDim.x + threadIdx.x;
    if (k >= nnz) return;
    int v = vertex[k];
    int e = edges[k];
    int p = atomicAdd(&d_curE[e], 1);
    d_csrE_v[d_offE[e] + p] = v;
    int q = atomicAdd(&d_curV[v], 1);
    d_csrV_e[d_offV[v] + q] = e;
}

// -------------------- distinct-degree (dense-H semantics) via CSR dedup, warp per row ----
__global__ void dedup_deg_kernel(int Me, int Nv)
{
    int warp = (blockIdx.x * blockDim.x + threadIdx.x) >> 5;
    int lane = threadIdx.x & 31;
    if (warp < Me) {
        int e = warp;
        int s = d_offE[e], t = d_offE[e + 1];
        int distinct = 0;
        for (int i = s + lane; i < t; i += 32) {
            int val = d_csrE_v[i];
            bool dup = false;
            for (int j = s; j < i; j++)
                if (d_csrE_v[j] == val) { dup = true; break; }
            if (!dup) distinct++;
        }
        distinct = __reduce_add_sync(0xffffffffu, distinct);
        if (lane == 0)
            d_sE[e] = rsqrtf((float)distinct) / ((float)(t - s) + 1e-8f);
    } else if (warp < Me + Nv) {
        int v = warp - Me;
        int s = d_offV[v], t = d_offV[v + 1];
        int distinct = 0;
        for (int i = s + lane; i < t; i += 32) {
            int val = d_csrV_e[i];
            bool dup = false;
            for (int j = s; j < i; j++)
                if (d_csrV_e[j] == val) { dup = true; break; }
            if (!dup) distinct++;
        }
        distinct = __reduce_add_sync(0xffffffffu, distinct);
        if (lane == 0)
            d_degV[v] = (distinct == 0) ? 1.0f : rsqrtf((float)distinct);
    }
}

// -------------------- SGEMM: Xp = X @ W^T  (K = 256), spill-proof 4x4 microtile ----------
#define BM 64
#define BN 64
#define BK 16

__global__ __launch_bounds__(256)
void sgemm_kernel(const float* __restrict__ A, const float* __restrict__ B,
                  float* __restrict__ Cmat, int Nrows)
{
    __shared__ float As[BK][BM];   // As[k][m]
    __shared__ float Bs[BK][BN];   // Bs[k][n]

    const int tid = threadIdx.x;
    const int brow0 = blockIdx.x * BM;
    const int bcol0 = blockIdx.y * BN;
    const int tx = tid & 15;       // n-group (16)
    const int ty = tid >> 4;       // m-group (16)

    // 4x4 accumulator in four float4 (16 registers) -- no arrays anywhere
    float4 c0 = make_float4(0.f, 0.f, 0.f, 0.f);
    float4 c1 = c0, c2 = c0, c3 = c0;

    // per-thread load coords: 256 threads, each one float4 of A and of B per tile
    const int lrow = tid >> 2;          // 0..63
    const int lk4  = (tid & 3) * 4;     // 0,4,8,12
    const int arow = brow0 + lrow;
    const bool aval = (arow < Nrows);
    const float4 z4 = make_float4(0.f, 0.f, 0.f, 0.f);

#pragma unroll 1
    for (int kt = 0; kt < CDIM; kt += BK) {
        float4 va = aval ? *(const float4*)&A[(long)arow * CDIM + kt + lk4] : z4;
        float4 vb = *(const float4*)&B[(long)(bcol0 + lrow) * CDIM + kt + lk4];
        __syncthreads();
        As[lk4 + 0][lrow] = va.x;
        As[lk4 + 1][lrow] = va.y;
        As[lk4 + 2][lrow] = va.z;
        As[lk4 + 3][lrow] = va.w;
        Bs[lk4 + 0][lrow] = vb.x;
        Bs[lk4 + 1][lrow] = vb.y;
        Bs[lk4 + 2][lrow] = vb.z;
        Bs[lk4 + 3][lrow] = vb.w;
        __syncthreads();
#pragma unroll
        for (int k = 0; k < BK; k++) {
            float4 af = *(const float4*)&As[k][ty * 4];
            float4 bf = *(const float4*)&Bs[k][tx * 4];
            c0.x += af.x * bf.x; c0.y += af.x * bf.y; c0.z += af.x * bf.z; c0.w += af.x * bf.w;
            c1.x += af.y * bf.x; c1.y += af.y * bf.y; c1.z += af.y * bf.z; c1.w += af.y * bf.w;
            c2.x += af.z * bf.x; c2.y += af.z * bf.y; c2.z += af.z * bf.z; c2.w += af.z * bf.w;
            c3.x += af.w * bf.x; c3.y += af.w * bf.y; c3.z += af.w * bf.z; c3.w += af.w * bf.w;
        }
    }

    const int orow = brow0 + ty * 4;
    const int ocol = bcol0 + tx * 4;
    if (orow + 0 < Nrows) *(float4*)&Cmat[(long)(orow + 0) * CDIM + ocol] = c0;
    if (orow + 1 < Nrows) *(float4*)&Cmat[(long)(orow + 1) * CDIM + ocol] = c1;
    if (orow + 2 < Nrows) *(float4*)&Cmat[(long)(orow + 2) * CDIM + ocol] = c2;
    if (orow + 3 < Nrows) *(float4*)&Cmat[(long)(orow + 3) * CDIM + ocol] = c3;
}

// -------------------- vertex -> edge: mean + edge norm (fused scale) --------------------
__global__ __launch_bounds__(CDIM)
void edge_gather_kernel(const float* __restrict__ Xp)
{
    int e = blockIdx.x;
    int c = threadIdx.x;
    int i = d_offE[e];
    int end = d_offE[e + 1];
    float s = d_sE[e];
    float acc = 0.0f;
    for (; i + 4 <= end; i += 4) {
        int v0 = d_csrE_v[i + 0];
        int v1 = d_csrE_v[i + 1];
        int v2 = d_csrE_v[i + 2];
        int v3 = d_csrE_v[i + 3];
        acc += Xp[(long)v0 * CDIM + c] + Xp[(long)v1 * CDIM + c]
             + Xp[(long)v2 * CDIM + c] + Xp[(long)v3 * CDIM + c];
    }
    for (; i < end; i++) acc += Xp[(long)d_csrE_v[i] * CDIM + c];
    d_Xe[(long)e * CDIM + c] = acc * s;
}

// -------------------- edge -> vertex: sum + vertex norm (fused scale) --------------------
__global__ __launch_bounds__(CDIM)
void vertex_gather_kernel(float* __restrict__ out)
{
    int v = blockIdx.x;
    int c = threadIdx.x;
    int i = d_offV[v];
    int end = d_offV[v + 1];
    float dv = d_degV[v];
    float acc = 0.0f;
    for (; i + 4 <= end; i += 4) {
        int e0 = d_csrV_e[i + 0];
        int e1 = d_csrV_e[i + 1];
        int e2 = d_csrV_e[i + 2];
        int e3 = d_csrV_e[i + 3];
        acc += d_Xe[(long)e0 * CDIM + c] + d_Xe[(long)e1 * CDIM + c]
             + d_Xe[(long)e2 * CDIM + c] + d_Xe[(long)e3 * CDIM + c];
    }
    for (; i < end; i++) acc += d_Xe[(long)d_csrV_e[i] * CDIM + c];
    out[(long)v * CDIM + c] = acc * dv;
}

// -------------------- launch --------------------
extern "C" void kernel_launch(void* const* d_in, const int* in_sizes, int n_in,
                              void* d_out, int out_size)
{
    const float* X      = (const float*)d_in[0];
    const float* W      = (const float*)d_in[1];
    const int*   vertex = (const int*)d_in[2];
    const int*   edges  = (const int*)d_in[3];
    // d_in[4] = H (dense incidence) -- intentionally unused; degrees come from CSR dedup
    float* out = (float*)d_out;

    int Nv  = in_sizes[0] / CDIM;             // 20000
    int NNZ = in_sizes[2];                    // 160000
    int Me  = (int)((long)in_sizes[4] / Nv);  // 4000

    zero_kernel<<<64, 256>>>(Me, Nv);
    count_kernel<<<(NNZ + 255) / 256, 256>>>(vertex, edges, NNZ);
    scan_kernel<<<1, 1024>>>(0, Me);
    scan_kernel<<<1, 1024>>>(1, Nv);
    fill_kernel<<<(NNZ + 255) / 256, 256>>>(vertex, edges, NNZ);
    {
        int warps = Me + Nv;
        int blocks = (warps * 32 + 255) / 256;
        dedup_deg_kernel<<<blocks, 256>>>(Me, Nv);
    }

    // GEMM writes Xp directly into d_out (scratch reuse; overwritten later)
    dim3 ggrid((Nv + BM - 1) / BM, CDIM / BN);
    sgemm_kernel<<<ggrid, 256>>>(X, W, out, Nv);

    edge_gather_kernel<<<Me, CDIM>>>(out);
    vertex_gather_kernel<<<Nv, CDIM>>>(out);
}

// round 5
// speedup vs baseline: 1.2354x; 1.2354x over previous
#include <cuda_runtime.h>
#include <cuda_bf16.h>

#define CDIM   256
#define CDIM4  64          // CDIM/4
#define NV_MAX 20000
#define ME_MAX 4000
#define NNZ_MAX 160000

// -------------------- static device scratch --------------------
// Xp lives in d_out (GEMM writes it, edge_gather reads it, vertex_gather overwrites it).
__device__ float4 d_Xe4[ME_MAX * CDIM4];   // per-edge aggregated (scaled)
__device__ int   d_cntE[ME_MAX];
__device__ int   d_cntV[NV_MAX];
__device__ int   d_offE[ME_MAX + 1];
__device__ int   d_offV[NV_MAX + 1];
__device__ int   d_curE[ME_MAX];
__device__ int   d_curV[NV_MAX];
__device__ int   d_csrE_v[NNZ_MAX];
__device__ int   d_csrV_e[NNZ_MAX];
__device__ float d_degV[NV_MAX];
__device__ float d_sE[ME_MAX];

// -------------------- zero counters --------------------
__global__ void zero_kernel(int Me, int Nv)
{
    int total = 2 * (Me + Nv);
    for (int i = blockIdx.x * blockDim.x + threadIdx.x; i < total;
         i += gridDim.x * blockDim.x) {
        int j = i;
        if (j < Me) { d_cntE[j] = 0; continue; } j -= Me;
        if (j < Me) { d_curE[j] = 0; continue; } j -= Me;
        if (j < Nv) { d_cntV[j] = 0; continue; } j -= Nv;
        d_curV[j] = 0;
    }
}

// -------------------- raw counts --------------------
__global__ void count_kernel(const int* __restrict__ vertex, const int* __restrict__ edges,
                             int nnz)
{
    int k = blockIdx.x * blockDim.x + threadIdx.x;
    if (k >= nnz) return;
    atomicAdd(&d_cntE[edges[k]], 1);
    atomicAdd(&d_cntV[vertex[k]], 1);
}

// -------------------- both exclusive scans in ONE launch (block 0: E, block 1: V) --------
// Shuffle-based: 3 __syncthreads total, scalar accumulators only.
__global__ void scan2_kernel(int Me, int Nv)
{
    int which = blockIdx.x;
    const int* __restrict__ in = which ? d_cntV : d_cntE;
    int* __restrict__ out      = which ? d_offV : d_offE;
    int L = which ? Nv : Me;

    __shared__ int warpsums[32];
    int tid  = threadIdx.x;            // 1024 threads
    int lane = tid & 31;
    int wid  = tid >> 5;
    int per  = (L + 1023) >> 10;
    int base = tid * per;

    int s = 0;
    for (int i = 0; i < per; i++) {
        int idx = base + i;
        if (idx < L) s += in[idx];
    }
    // warp-inclusive scan of per-thread sums
    int x = s;
#pragma unroll
    for (int o = 1; o < 32; o <<= 1) {
        int y = __shfl_up_sync(0xffffffffu, x, o);
        if (lane >= o) x += y;
    }
    if (lane == 31) warpsums[wid] = x;
    __syncthreads();
    if (wid == 0) {
        int w = warpsums[lane];
#pragma unroll
        for (int o = 1; o < 32; o <<= 1) {
            int y = __shfl_up_sync(0xffffffffu, w, o);
            if (lane >= o) w += y;
        }
        warpsums[lane] = w;
    }
    __syncthreads();
    int warpoff = (wid == 0) ? 0 : warpsums[wid - 1];
    int run = warpoff + x - s;          // exclusive prefix for this thread's chunk
    for (int i = 0; i < per; i++) {
        int idx = base + i;
        if (idx < L) { out[idx] = run; run += in[idx]; }
    }
    if (tid == 1023) out[L] = warpsums[31];
}

// -------------------- CSR fill --------------------
__global__ void fill_kernel(const int* __restrict__ vertex, const int* __restrict__ edges, int nnz)
{
    int k = blockIdx.x * blockDim.x + threadIdx.x;
    if (k >= nnz) return;
    int v = vertex[k];
    int e = edges[k];
    int p = atomicAdd(&d_curE[e], 1);
    d_csrE_v[d_offE[e] + p] = v;
    int q = atomicAdd(&d_curV[v], 1);
    d_csrV_e[d_offV[v] + q] = e;
}

// -------------------- distinct-degree (dense-H semantics) via CSR dedup, warp per row ----
__global__ void dedup_deg_kernel(int Me, int Nv)
{
    int warp = (blockIdx.x * blockDim.x + threadIdx.x) >> 5;
    int lane = threadIdx.x & 31;
    if (warp < Me) {
        int e = warp;
        int s = d_offE[e], t = d_offE[e + 1];
        int distinct = 0;
        for (int i = s + lane; i < t; i += 32) {
            int val = d_csrE_v[i];
            bool dup = false;
            for (int j = s; j < i; j++)
                if (d_csrE_v[j] == val) { dup = true; break; }
            if (!dup) distinct++;
        }
        distinct = __reduce_add_sync(0xffffffffu, distinct);
        if (lane == 0)
            d_sE[e] = rsqrtf((float)distinct) / ((float)(t - s) + 1e-8f);
    } else if (warp < Me + Nv) {
        int v = warp - Me;
        int s = d_offV[v], t = d_offV[v + 1];
        int distinct = 0;
        for (int i = s + lane; i < t; i += 32) {
            int val = d_csrV_e[i];
            bool dup = false;
            for (int j = s; j < i; j++)
                if (d_csrV_e[j] == val) { dup = true; break; }
            if (!dup) distinct++;
        }
        distinct = __reduce_add_sync(0xffffffffu, distinct);
        if (lane == 0)
            d_degV[v] = (distinct == 0) ? 1.0f : rsqrtf((float)distinct);
    }
}

// -------------------- SGEMM: Xp = X @ W^T  (K=256), 128x64 tile, 8x4 microtile ----------
#define BM 128
#define BN 64
#define BK 16

__global__ __launch_bounds__(256)
void sgemm_kernel(const float* __restrict__ A, const float* __restrict__ B,
                  float* __restrict__ Cmat, int Nrows)
{
    __shared__ float As[BK][BM];   // 8 KB
    __shared__ float Bs[BK][BN];   // 4 KB

    const int tid = threadIdx.x;
    const int brow0 = blockIdx.x * BM;
    const int bcol0 = blockIdx.y * BN;
    const int tx = tid & 15;       // n-group: 4 cols
    const int ty = tid >> 4;       // m-group: 8 rows

    // 8x4 accumulator: eight NAMED float4 (no arrays -> no spill)
    float4 c0 = make_float4(0.f,0.f,0.f,0.f);
    float4 c1 = c0, c2 = c0, c3 = c0, c4 = c0, c5 = c0, c6 = c0, c7 = c0;

    // A loads: 2 float4/thread; B loads: 1 float4/thread
    const int a0row = tid >> 2;              // 0..63
    const int a1row = a0row + 64;            // 64..127
    const int lk4   = (tid & 3) * 4;         // 0,4,8,12
    const int ga0 = brow0 + a0row;
    const int ga1 = brow0 + a1row;
    const bool v0 = (ga0 < Nrows);
    const bool v1 = (ga1 < Nrows);
    const int gb  = bcol0 + a0row;           // a0row doubles as B row (0..63)
    const float4 z4 = make_float4(0.f,0.f,0.f,0.f);

#pragma unroll 1
    for (int kt = 0; kt < CDIM; kt += BK) {
        float4 va0 = v0 ? *(const float4*)&A[(long)ga0 * CDIM + kt + lk4] : z4;
        float4 va1 = v1 ? *(const float4*)&A[(long)ga1 * CDIM + kt + lk4] : z4;
        float4 vb  = *(const float4*)&B[(long)gb * CDIM + kt + lk4];
        __syncthreads();
        As[lk4 + 0][a0row] = va0.x;  As[lk4 + 1][a0row] = va0.y;
        As[lk4 + 2][a0row] = va0.z;  As[lk4 + 3][a0row] = va0.w;
        As[lk4 + 0][a1row] = va1.x;  As[lk4 + 1][a1row] = va1.y;
        As[lk4 + 2][a1row] = va1.z;  As[lk4 + 3][a1row] = va1.w;
        Bs[lk4 + 0][a0row] = vb.x;   Bs[lk4 + 1][a0row] = vb.y;
        Bs[lk4 + 2][a0row] = vb.z;   Bs[lk4 + 3][a0row] = vb.w;
        __syncthreads();
#pragma unroll
        for (int k = 0; k < BK; k++) {
            float4 af0 = *(const float4*)&As[k][ty * 8];
            float4 af1 = *(const float4*)&As[k][ty * 8 + 4];
            float4 bf  = *(const float4*)&Bs[k][tx * 4];
            c0.x += af0.x * bf.x; c0.y += af0.x * bf.y; c0.z += af0.x * bf.z; c0.w += af0.x * bf.w;
            c1.x += af0.y * bf.x; c1.y += af0.y * bf.y; c1.z += af0.y * bf.z; c1.w += af0.y * bf.w;
            c2.x += af0.z * bf.x; c2.y += af0.z * bf.y; c2.z += af0.z * bf.z; c2.w += af0.z * bf.w;
            c3.x += af0.w * bf.x; c3.y += af0.w * bf.y; c3.z += af0.w * bf.z; c3.w += af0.w * bf.w;
            c4.x += af1.x * bf.x; c4.y += af1.x * bf.y; c4.z += af1.x * bf.z; c4.w += af1.x * bf.w;
            c5.x += af1.y * bf.x; c5.y += af1.y * bf.y; c5.z += af1.y * bf.z; c5.w += af1.y * bf.w;
            c6.x += af1.z * bf.x; c6.y += af1.z * bf.y; c6.z += af1.z * bf.z; c6.w += af1.z * bf.w;
            c7.x += af1.w * bf.x; c7.y += af1.w * bf.y; c7.z += af1.w * bf.z; c7.w += af1.w * bf.w;
        }
    }

    const int orow = brow0 + ty * 8;
    const int ocol = bcol0 + tx * 4;
    if (orow + 0 < Nrows) *(float4*)&Cmat[(long)(orow + 0) * CDIM + ocol] = c0;
    if (orow + 1 < Nrows) *(float4*)&Cmat[(long)(orow + 1) * CDIM + ocol] = c1;
    if (orow + 2 < Nrows) *(float4*)&Cmat[(long)(orow + 2) * CDIM + ocol] = c2;
    if (orow + 3 < Nrows) *(float4*)&Cmat[(long)(orow + 3) * CDIM + ocol] = c3;
    if (orow + 4 < Nrows) *(float4*)&Cmat[(long)(orow + 4) * CDIM + ocol] = c4;
    if (orow + 5 < Nrows) *(float4*)&Cmat[(long)(orow + 5) * CDIM + ocol] = c5;
    if (orow + 6 < Nrows) *(float4*)&Cmat[(long)(orow + 6) * CDIM + ocol] = c6;
    if (orow + 7 < Nrows) *(float4*)&Cmat[(long)(orow + 7) * CDIM + ocol] = c7;
}

// -------------------- vertex -> edge: mean + edge norm, float4 --------------------
__global__ __launch_bounds__(CDIM4)
void edge_gather_kernel(const float4* __restrict__ Xp4)
{
    int e = blockIdx.x;
    int c = threadIdx.x;                 // 0..63
    int i = d_offE[e];
    int end = d_offE[e + 1];
    float s = d_sE[e];
    float4 acc = make_float4(0.f,0.f,0.f,0.f);
    for (; i + 2 <= end; i += 2) {
        float4 p0 = Xp4[(long)d_csrE_v[i + 0] * CDIM4 + c];
        float4 p1 = Xp4[(long)d_csrE_v[i + 1] * CDIM4 + c];
        acc.x += p0.x + p1.x; acc.y += p0.y + p1.y;
        acc.z += p0.z + p1.z; acc.w += p0.w + p1.w;
    }
    for (; i < end; i++) {
        float4 p = Xp4[(long)d_csrE_v[i] * CDIM4 + c];
        acc.x += p.x; acc.y += p.y; acc.z += p.z; acc.w += p.w;
    }
    d_Xe4[(long)e * CDIM4 + c] = make_float4(acc.x * s, acc.y * s, acc.z * s, acc.w * s);
}

// -------------------- edge -> vertex: sum + vertex norm, float4 --------------------
__global__ __launch_bounds__(CDIM4)
void vertex_gather_kernel(float4* __restrict__ out4)
{
    int v = blockIdx.x;
    int c = threadIdx.x;                 // 0..63
    int i = d_offV[v];
    int end = d_offV[v + 1];
    float dv = d_degV[v];
    float4 acc = make_float4(0.f,0.f,0.f,0.f);
    for (; i + 2 <= end; i += 2) {
        float4 p0 = d_Xe4[(long)d_csrV_e[i + 0] * CDIM4 + c];
        float4 p1 = d_Xe4[(long)d_csrV_e[i + 1] * CDIM4 + c];
        acc.x += p0.x + p1.x; acc.y += p0.y + p1.y;
        acc.z += p0.z + p1.z; acc.w += p0.w + p1.w;
    }
    for (; i < end; i++) {
        float4 p = d_Xe4[(long)d_csrV_e[i] * CDIM4 + c];
        acc.x += p.x; acc.y += p.y; acc.z += p.z; acc.w += p.w;
    }
    out4[(long)v * CDIM4 + c] = make_float4(acc.x * dv, acc.y * dv, acc.z * dv, acc.w * dv);
}

// -------------------- launch --------------------
extern "C" void kernel_launch(void* const* d_in, const int* in_sizes, int n_in,
                              void* d_out, int out_size)
{
    const float* X      = (const float*)d_in[0];
    const float* W      = (const float*)d_in[1];
    const int*   vertex = (const int*)d_in[2];
    const int*   edges  = (const int*)d_in[3];
    float* out = (float*)d_out;

    int Nv  = in_sizes[0] / CDIM;             // 20000
    int NNZ = in_sizes[2];                    // 160000
    int Me  = (int)((long)in_sizes[4] / Nv);  // 4000

    zero_kernel<<<64, 256>>>(Me, Nv);
    count_kernel<<<(NNZ + 255) / 256, 256>>>(vertex, edges, NNZ);
    scan2_kernel<<<2, 1024>>>(Me, Nv);
    fill_kernel<<<(NNZ + 255) / 256, 256>>>(vertex, edges, NNZ);
    {
        int warps = Me + Nv;
        int blocks = (warps * 32 + 255) / 256;
        dedup_deg_kernel<<<blocks, 256>>>(Me, Nv);
    }

    dim3 ggrid((Nv + BM - 1) / BM, CDIM / BN);
    sgemm_kernel<<<ggrid, 256>>>(X, W, out, Nv);

    edge_gather_kernel<<<Me, CDIM4>>>((const float4*)out);
    vertex_gather_kernel<<<Nv, CDIM4>>>((float4*)out);
}

// round 6
// speedup vs baseline: 1.4079x; 1.1396x over previous
#include <cuda_runtime.h>
#include <cuda_bf16.h>

#define CDIM   256
#define CDIM4  64          // CDIM/4
#define NV_MAX 20000
#define ME_MAX 4000
#define NNZ_MAX 160000

// -------------------- static device scratch --------------------
// Xp lives in d_out (GEMM writes it, edge_gather reads it, vertex_gather overwrites it).
__device__ float4 d_Xe4[ME_MAX * CDIM4];   // per-edge aggregated (scaled)
__device__ int   d_cntE[ME_MAX];
__device__ int   d_cntV[NV_MAX];
__device__ int   d_offE[ME_MAX + 1];
__device__ int   d_offV[NV_MAX + 1];
__device__ int   d_curE[ME_MAX];
__device__ int   d_curV[NV_MAX];
__device__ int   d_csrE_v[NNZ_MAX];
__device__ int   d_csrV_e[NNZ_MAX];
__device__ float d_degV[NV_MAX];
__device__ float d_sE[ME_MAX];

// -------------------- zero counters --------------------
__global__ void zero_kernel(int Me, int Nv)
{
    int total = 2 * (Me + Nv);
    for (int i = blockIdx.x * blockDim.x + threadIdx.x; i < total;
         i += gridDim.x * blockDim.x) {
        int j = i;
        if (j < Me) { d_cntE[j] = 0; continue; } j -= Me;
        if (j < Me) { d_curE[j] = 0; continue; } j -= Me;
        if (j < Nv) { d_cntV[j] = 0; continue; } j -= Nv;
        d_curV[j] = 0;
    }
}

// -------------------- raw counts --------------------
__global__ void count_kernel(const int* __restrict__ vertex, const int* __restrict__ edges,
                             int nnz)
{
    int k = blockIdx.x * blockDim.x + threadIdx.x;
    if (k >= nnz) return;
    atomicAdd(&d_cntE[edges[k]], 1);
    atomicAdd(&d_cntV[vertex[k]], 1);
}

// -------------------- both exclusive scans in ONE launch (block 0: E, block 1: V) --------
__global__ void scan2_kernel(int Me, int Nv)
{
    int which = blockIdx.x;
    const int* __restrict__ in = which ? d_cntV : d_cntE;
    int* __restrict__ out      = which ? d_offV : d_offE;
    int L = which ? Nv : Me;

    __shared__ int warpsums[32];
    int tid  = threadIdx.x;            // 1024 threads
    int lane = tid & 31;
    int wid  = tid >> 5;
    int per  = (L + 1023) >> 10;
    int base = tid * per;

    int s = 0;
    for (int i = 0; i < per; i++) {
        int idx = base + i;
        if (idx < L) s += in[idx];
    }
    int x = s;
#pragma unroll
    for (int o = 1; o < 32; o <<= 1) {
        int y = __shfl_up_sync(0xffffffffu, x, o);
        if (lane >= o) x += y;
    }
    if (lane == 31) warpsums[wid] = x;
    __syncthreads();
    if (wid == 0) {
        int w = warpsums[lane];
#pragma unroll
        for (int o = 1; o < 32; o <<= 1) {
            int y = __shfl_up_sync(0xffffffffu, w, o);
            if (lane >= o) w += y;
        }
        warpsums[lane] = w;
    }
    __syncthreads();
    int warpoff = (wid == 0) ? 0 : warpsums[wid - 1];
    int run = warpoff + x - s;
    for (int i = 0; i < per; i++) {
        int idx = base + i;
        if (idx < L) { out[idx] = run; run += in[idx]; }
    }
    if (tid == 1023) out[L] = warpsums[31];
}

// -------------------- CSR fill --------------------
__global__ void fill_kernel(const int* __restrict__ vertex, const int* __restrict__ edges, int nnz)
{
    int k = blockIdx.x * blockDim.x + threadIdx.x;
    if (k >= nnz) return;
    int v = vertex[k];
    int e = edges[k];
    int p = atomicAdd(&d_curE[e], 1);
    d_csrE_v[d_offE[e] + p] = v;
    int q = atomicAdd(&d_curV[v], 1);
    d_csrV_e[d_offV[v] + q] = e;
}

// -------------------- distinct-degree (dense-H semantics) via CSR dedup, warp per row ----
__global__ void dedup_deg_kernel(int Me, int Nv)
{
    int warp = (blockIdx.x * blockDim.x + threadIdx.x) >> 5;
    int lane = threadIdx.x & 31;
    if (warp < Me) {
        int e = warp;
        int s = d_offE[e], t = d_offE[e + 1];
        int distinct = 0;
        for (int i = s + lane; i < t; i += 32) {
            int val = d_csrE_v[i];
            bool dup = false;
            for (int j = s; j < i; j++)
                if (d_csrE_v[j] == val) { dup = true; break; }
            if (!dup) distinct++;
        }
        distinct = __reduce_add_sync(0xffffffffu, distinct);
        if (lane == 0)
            d_sE[e] = rsqrtf((float)distinct) / ((float)(t - s) + 1e-8f);
    } else if (warp < Me + Nv) {
        int v = warp - Me;
        int s = d_offV[v], t = d_offV[v + 1];
        int distinct = 0;
        for (int i = s + lane; i < t; i += 32) {
            int val = d_csrV_e[i];
            bool dup = false;
            for (int j = s; j < i; j++)
                if (d_csrV_e[j] == val) { dup = true; break; }
            if (!dup) distinct++;
        }
        distinct = __reduce_add_sync(0xffffffffu, distinct);
        if (lane == 0)
            d_degV[v] = (distinct == 0) ? 1.0f : rsqrtf((float)distinct);
    }
}

// -------------------- SGEMM: Xp = X @ W^T (K=256), 128x64 tile, double-buffered ---------
#define BM 128
#define BN 64
#define BK 16

__global__ __launch_bounds__(256)
void sgemm_kernel(const float* __restrict__ A, const float* __restrict__ B,
                  float* __restrict__ Cmat, int Nrows)
{
    __shared__ float As[2][BK][BM];   // 16 KB
    __shared__ float Bs[2][BK][BN];   // 8 KB

    const int tid = threadIdx.x;
    const int brow0 = blockIdx.x * BM;
    const int bcol0 = blockIdx.y * BN;
    const int tx = tid & 15;       // n-group: 4 cols
    const int ty = tid >> 4;       // m-group: 8 rows

    float4 c0 = make_float4(0.f,0.f,0.f,0.f);
    float4 c1 = c0, c2 = c0, c3 = c0, c4 = c0, c5 = c0, c6 = c0, c7 = c0;

    const int a0row = tid >> 2;              // 0..63
    const int a1row = a0row + 64;            // 64..127
    const int lk4   = (tid & 3) * 4;         // 0,4,8,12
    const int ga0 = brow0 + a0row;
    const int ga1 = brow0 + a1row;
    const bool av0 = (ga0 < Nrows);
    const bool av1 = (ga1 < Nrows);
    const int gb  = bcol0 + a0row;
    const float4 z4 = make_float4(0.f,0.f,0.f,0.f);

    // prologue: tile 0 into buf 0
    {
        float4 va0 = av0 ? *(const float4*)&A[(long)ga0 * CDIM + lk4] : z4;
        float4 va1 = av1 ? *(const float4*)&A[(long)ga1 * CDIM + lk4] : z4;
        float4 vb  = *(const float4*)&B[(long)gb * CDIM + lk4];
        As[0][lk4 + 0][a0row] = va0.x;  As[0][lk4 + 1][a0row] = va0.y;
        As[0][lk4 + 2][a0row] = va0.z;  As[0][lk4 + 3][a0row] = va0.w;
        As[0][lk4 + 0][a1row] = va1.x;  As[0][lk4 + 1][a1row] = va1.y;
        As[0][lk4 + 2][a1row] = va1.z;  As[0][lk4 + 3][a1row] = va1.w;
        Bs[0][lk4 + 0][a0row] = vb.x;   Bs[0][lk4 + 1][a0row] = vb.y;
        Bs[0][lk4 + 2][a0row] = vb.z;   Bs[0][lk4 + 3][a0row] = vb.w;
    }
    __syncthreads();

    int buf = 0;
#pragma unroll 1
    for (int t = 0; t < CDIM / BK; t++) {
        float4 na0, na1, nb;
        const bool more = (t < CDIM / BK - 1);
        if (more) {
            int kt = (t + 1) * BK;
            na0 = av0 ? *(const float4*)&A[(long)ga0 * CDIM + kt + lk4] : z4;
            na1 = av1 ? *(const float4*)&A[(long)ga1 * CDIM + kt + lk4] : z4;
            nb  = *(const float4*)&B[(long)gb * CDIM + kt + lk4];
        }
#pragma unroll
        for (int k = 0; k < BK; k++) {
            float4 af0 = *(const float4*)&As[buf][k][ty * 8];
            float4 af1 = *(const float4*)&As[buf][k][ty * 8 + 4];
            float4 bf  = *(const float4*)&Bs[buf][k][tx * 4];
            c0.x += af0.x * bf.x; c0.y += af0.x * bf.y; c0.z += af0.x * bf.z; c0.w += af0.x * bf.w;
            c1.x += af0.y * bf.x; c1.y += af0.y * bf.y; c1.z += af0.y * bf.z; c1.w += af0.y * bf.w;
            c2.x += af0.z * bf.x; c2.y += af0.z * bf.y; c2.z += af0.z * bf.z; c2.w += af0.z * bf.w;
            c3.x += af0.w * bf.x; c3.y += af0.w * bf.y; c3.z += af0.w * bf.z; c3.w += af0.w * bf.w;
            c4.x += af1.x * bf.x; c4.y += af1.x * bf.y; c4.z += af1.x * bf.z; c4.w += af1.x * bf.w;
            c5.x += af1.y * bf.x; c5.y += af1.y * bf.y; c5.z += af1.y * bf.z; c5.w += af1.y * bf.w;
            c6.x += af1.z * bf.x; c6.y += af1.z * bf.y; c6.z += af1.z * bf.z; c6.w += af1.z * bf.w;
            c7.x += af1.w * bf.x; c7.y += af1.w * bf.y; c7.z += af1.w * bf.z; c7.w += af1.w * bf.w;
        }
        if (more) {
            int nbuf = buf ^ 1;
            As[nbuf][lk4 + 0][a0row] = na0.x;  As[nbuf][lk4 + 1][a0row] = na0.y;
            As[nbuf][lk4 + 2][a0row] = na0.z;  As[nbuf][lk4 + 3][a0row] = na0.w;
            As[nbuf][lk4 + 0][a1row] = na1.x;  As[nbuf][lk4 + 1][a1row] = na1.y;
            As[nbuf][lk4 + 2][a1row] = na1.z;  As[nbuf][lk4 + 3][a1row] = na1.w;
            Bs[nbuf][lk4 + 0][a0row] = nb.x;   Bs[nbuf][lk4 + 1][a0row] = nb.y;
            Bs[nbuf][lk4 + 2][a0row] = nb.z;   Bs[nbuf][lk4 + 3][a0row] = nb.w;
        }
        __syncthreads();
        buf ^= 1;
    }

    const int orow = brow0 + ty * 8;
    const int ocol = bcol0 + tx * 4;
    if (orow + 0 < Nrows) *(float4*)&Cmat[(long)(orow + 0) * CDIM + ocol] = c0;
    if (orow + 1 < Nrows) *(float4*)&Cmat[(long)(orow + 1) * CDIM + ocol] = c1;
    if (orow + 2 < Nrows) *(float4*)&Cmat[(long)(orow + 2) * CDIM + ocol] = c2;
    if (orow + 3 < Nrows) *(float4*)&Cmat[(long)(orow + 3) * CDIM + ocol] = c3;
    if (orow + 4 < Nrows) *(float4*)&Cmat[(long)(orow + 4) * CDIM + ocol] = c4;
    if (orow + 5 < Nrows) *(float4*)&Cmat[(long)(orow + 5) * CDIM + ocol] = c5;
    if (orow + 6 < Nrows) *(float4*)&Cmat[(long)(orow + 6) * CDIM + ocol] = c6;
    if (orow + 7 < Nrows) *(float4*)&Cmat[(long)(orow + 7) * CDIM + ocol] = c7;
}

// -------------------- vertex -> edge: mean + edge norm, float4 --------------------
__global__ __launch_bounds__(CDIM4)
void edge_gather_kernel(const float4* __restrict__ Xp4)
{
    int e = blockIdx.x;
    int c = threadIdx.x;                 // 0..63
    int i = d_offE[e];
    int end = d_offE[e + 1];
    float s = d_sE[e];
    float4 acc = make_float4(0.f,0.f,0.f,0.f);
    for (; i + 2 <= end; i += 2) {
        float4 p0 = Xp4[(long)d_csrE_v[i + 0] * CDIM4 + c];
        float4 p1 = Xp4[(long)d_csrE_v[i + 1] * CDIM4 + c];
        acc.x += p0.x + p1.x; acc.y += p0.y + p1.y;
        acc.z += p0.z + p1.z; acc.w += p0.w + p1.w;
    }
    for (; i < end; i++) {
        float4 p = Xp4[(long)d_csrE_v[i] * CDIM4 + c];
        acc.x += p.x; acc.y += p.y; acc.z += p.z; acc.w += p.w;
    }
    d_Xe4[(long)e * CDIM4 + c] = make_float4(acc.x * s, acc.y * s, acc.z * s, acc.w * s);
}

// -------------------- edge -> vertex: sum + vertex norm, float4 --------------------
__global__ __launch_bounds__(CDIM4)
void vertex_gather_kernel(float4* __restrict__ out4)
{
    int v = blockIdx.x;
    int c = threadIdx.x;                 // 0..63
    int i = d_offV[v];
    int end = d_offV[v + 1];
    float dv = d_degV[v];
    float4 acc = make_float4(0.f,0.f,0.f,0.f);
    for (; i + 2 <= end; i += 2) {
        float4 p0 = d_Xe4[(long)d_csrV_e[i + 0] * CDIM4 + c];
        float4 p1 = d_Xe4[(long)d_csrV_e[i + 1] * CDIM4 + c];
        acc.x += p0.x + p1.x; acc.y += p0.y + p1.y;
        acc.z += p0.z + p1.z; acc.w += p0.w + p1.w;
    }
    for (; i < end; i++) {
        float4 p = d_Xe4[(long)d_csrV_e[i] * CDIM4 + c];
        acc.x += p.x; acc.y += p.y; acc.z += p.z; acc.w += p.w;
    }
    out4[(long)v * CDIM4 + c] = make_float4(acc.x * dv, acc.y * dv, acc.z * dv, acc.w * dv);
}

// -------------------- launch (prep chain forked onto a 2nd stream, overlapped with GEMM) --
extern "C" void kernel_launch(void* const* d_in, const int* in_sizes, int n_in,
                              void* d_out, int out_size)
{
    const float* X      = (const float*)d_in[0];
    const float* W      = (const float*)d_in[1];
    const int*   vertex = (const int*)d_in[2];
    const int*   edges  = (const int*)d_in[3];
    float* out = (float*)d_out;

    int Nv  = in_sizes[0] / CDIM;             // 20000
    int NNZ = in_sizes[2];                    // 160000
    int Me  = (int)((long)in_sizes[4] / Nv);  // 4000

    // One-time host-side resources (no device memory involved)
    static cudaStream_t s2 = nullptr;
    static cudaEvent_t evFork = nullptr, evJoin = nullptr;
    if (s2 == nullptr) {
        cudaStreamCreateWithFlags(&s2, cudaStreamNonBlocking);
        cudaEventCreateWithFlags(&evFork, cudaEventDisableTiming);
        cudaEventCreateWithFlags(&evJoin, cudaEventDisableTiming);
    }

    // fork: prep chain on s2, GEMM on the main (capture) stream
    cudaEventRecord(evFork, 0);
    cudaStreamWaitEvent(s2, evFork, 0);

    zero_kernel<<<64, 256, 0, s2>>>(Me, Nv);
    count_kernel<<<(NNZ + 255) / 256, 256, 0, s2>>>(vertex, edges, NNZ);
    scan2_kernel<<<2, 1024, 0, s2>>>(Me, Nv);
    fill_kernel<<<(NNZ + 255) / 256, 256, 0, s2>>>(vertex, edges, NNZ);
    {
        int warps = Me + Nv;
        int blocks = (warps * 32 + 255) / 256;
        dedup_deg_kernel<<<blocks, 256, 0, s2>>>(Me, Nv);
    }
    cudaEventRecord(evJoin, s2);

    dim3 ggrid((Nv + BM - 1) / BM, CDIM / BN);
    sgemm_kernel<<<ggrid, 256>>>(X, W, out, Nv);

    // join: gathers need both GEMM output and CSR/degree data
    cudaStreamWaitEvent(0, evJoin, 0);

    edge_gather_kernel<<<Me, CDIM4>>>((const float4*)out);
    vertex_gather_kernel<<<Nv, CDIM4>>>((float4*)out);
}

// round 7
// speedup vs baseline: 2.1890x; 1.5548x over previous
#include <cuda_runtime.h>
#include <cuda_bf16.h>

#define CDIM   256
#define CDIM4  64          // CDIM/4
#define NV_MAX 20000
#define ME_MAX 4000
#define NNZ_MAX 160000

// -------------------- static device scratch --------------------
__device__ float4 d_Y4[ME_MAX * CDIM4];    // edge-aggregated RAW X (scaled by sE)  [4 MB]
__device__ float4 d_XeP4[ME_MAX * CDIM4];  // projected edge features Y @ W^T       [4 MB]
__device__ int   d_cntE[ME_MAX];
__device__ int   d_cntV[NV_MAX];
__device__ int   d_offE[ME_MAX + 1];
__device__ int   d_offV[NV_MAX + 1];
__device__ int   d_curE[ME_MAX];
__device__ int   d_curV[NV_MAX];
__device__ int   d_csrE_v[NNZ_MAX];
__device__ int   d_csrV_e[NNZ_MAX];
__device__ float d_degV[NV_MAX];
__device__ float d_sE[ME_MAX];

// -------------------- zeroing (split E / V) --------------------
__global__ void zeroE_kernel(int Me)
{
    int i = blockIdx.x * blockDim.x + threadIdx.x;
    if (i < Me) { d_cntE[i] = 0; d_curE[i] = 0; }
}
__global__ void zeroV_kernel(int Nv)
{
    int i = blockIdx.x * blockDim.x + threadIdx.x;
    if (i < Nv) { d_cntV[i] = 0; d_curV[i] = 0; }
}

// -------------------- raw counts (split E / V) --------------------
__global__ void countE_kernel(const int* __restrict__ edges, int nnz)
{
    int k = blockIdx.x * blockDim.x + threadIdx.x;
    if (k < nnz) atomicAdd(&d_cntE[edges[k]], 1);
}
__global__ void countV_kernel(const int* __restrict__ vertex, int nnz)
{
    int k = blockIdx.x * blockDim.x + threadIdx.x;
    if (k < nnz) atomicAdd(&d_cntV[vertex[k]], 1);
}

// -------------------- single-block exclusive scan, shuffle-based --------------------
__global__ void scan_kernel(int which, int L)   // 0: cntE->offE, 1: cntV->offV
{
    const int* __restrict__ in = which ? d_cntV : d_cntE;
    int* __restrict__ out      = which ? d_offV : d_offE;

    __shared__ int warpsums[32];
    int tid  = threadIdx.x;            // 1024 threads
    int lane = tid & 31;
    int wid  = tid >> 5;
    int per  = (L + 1023) >> 10;
    int base = tid * per;

    int s = 0;
    for (int i = 0; i < per; i++) {
        int idx = base + i;
        if (idx < L) s += in[idx];
    }
    int x = s;
#pragma unroll
    for (int o = 1; o < 32; o <<= 1) {
        int y = __shfl_up_sync(0xffffffffu, x, o);
        if (lane >= o) x += y;
    }
    if (lane == 31) warpsums[wid] = x;
    __syncthreads();
    if (wid == 0) {
        int w = warpsums[lane];
#pragma unroll
        for (int o = 1; o < 32; o <<= 1) {
            int y = __shfl_up_sync(0xffffffffu, w, o);
            if (lane >= o) w += y;
        }
        warpsums[lane] = w;
    }
    __syncthreads();
    int warpoff = (wid == 0) ? 0 : warpsums[wid - 1];
    int run = warpoff + x - s;
    for (int i = 0; i < per; i++) {
        int idx = base + i;
        if (idx < L) { out[idx] = run; run += in[idx]; }
    }
    if (tid == 1023) out[L] = warpsums[31];
}

// -------------------- CSR fill (split E / V) --------------------
__global__ void fillE_kernel(const int* __restrict__ vertex, const int* __restrict__ edges, int nnz)
{
    int k = blockIdx.x * blockDim.x + threadIdx.x;
    if (k >= nnz) return;
    int e = edges[k];
    int p = atomicAdd(&d_curE[e], 1);
    d_csrE_v[d_offE[e] + p] = vertex[k];
}
__global__ void fillV_kernel(const int* __restrict__ vertex, const int* __restrict__ edges, int nnz)
{
    int k = blockIdx.x * blockDim.x + threadIdx.x;
    if (k >= nnz) return;
    int v = vertex[k];
    int q = atomicAdd(&d_curV[v], 1);
    d_csrV_e[d_offV[v] + q] = edges[k];
}

// -------------------- distinct-degree (dense-H semantics), warp per row --------------------
__global__ void dedupE_kernel(int Me)
{
    int e = (blockIdx.x * blockDim.x + threadIdx.x) >> 5;
    int lane = threadIdx.x & 31;
    if (e >= Me) return;
    int s = d_offE[e], t = d_offE[e + 1];
    int distinct = 0;
    for (int i = s + lane; i < t; i += 32) {
        int val = d_csrE_v[i];
        bool dup = false;
        for (int j = s; j < i; j++)
            if (d_csrE_v[j] == val) { dup = true; break; }
        if (!dup) distinct++;
    }
    distinct = __reduce_add_sync(0xffffffffu, distinct);
    if (lane == 0)
        d_sE[e] = rsqrtf((float)distinct) / ((float)(t - s) + 1e-8f);
}
__global__ void dedupV_kernel(int Nv)
{
    int v = (blockIdx.x * blockDim.x + threadIdx.x) >> 5;
    int lane = threadIdx.x & 31;
    if (v >= Nv) return;
    int s = d_offV[v], t = d_offV[v + 1];
    int distinct = 0;
    for (int i = s + lane; i < t; i += 32) {
        int val = d_csrV_e[i];
        bool dup = false;
        for (int j = s; j < i; j++)
            if (d_csrV_e[j] == val) { dup = true; break; }
        if (!dup) distinct++;
    }
    distinct = __reduce_add_sync(0xffffffffu, distinct);
    if (lane == 0)
        d_degV[v] = (distinct == 0) ? 1.0f : rsqrtf((float)distinct);
}

// -------------------- vertex -> edge on RAW X: mean + edge norm, float4 ------------------
__global__ __launch_bounds__(CDIM4)
void edge_gather_kernel(const float4* __restrict__ X4)
{
    int e = blockIdx.x;
    int c = threadIdx.x;                 // 0..63
    int i = d_offE[e];
    int end = d_offE[e + 1];
    float s = d_sE[e];
    float4 acc = make_float4(0.f,0.f,0.f,0.f);
    for (; i + 2 <= end; i += 2) {
        float4 p0 = X4[(long)d_csrE_v[i + 0] * CDIM4 + c];
        float4 p1 = X4[(long)d_csrE_v[i + 1] * CDIM4 + c];
        acc.x += p0.x + p1.x; acc.y += p0.y + p1.y;
        acc.z += p0.z + p1.z; acc.w += p0.w + p1.w;
    }
    for (; i < end; i++) {
        float4 p = X4[(long)d_csrE_v[i] * CDIM4 + c];
        acc.x += p.x; acc.y += p.y; acc.z += p.z; acc.w += p.w;
    }
    d_Y4[(long)e * CDIM4 + c] = make_float4(acc.x * s, acc.y * s, acc.z * s, acc.w * s);
}

// -------------------- SGEMM: XeP = Y @ W^T (M=4000, K=256), double-buffered --------------
#define BM 128
#define BN 64
#define BK 16

__global__ __launch_bounds__(256)
void sgemm_kernel(const float* __restrict__ A, const float* __restrict__ B,
                  float* __restrict__ Cmat, int Nrows)
{
    __shared__ float As[2][BK][BM];
    __shared__ float Bs[2][BK][BN];

    const int tid = threadIdx.x;
    const int brow0 = blockIdx.x * BM;
    const int bcol0 = blockIdx.y * BN;
    const int tx = tid & 15;
    const int ty = tid >> 4;

    float4 c0 = make_float4(0.f,0.f,0.f,0.f);
    float4 c1 = c0, c2 = c0, c3 = c0, c4 = c0, c5 = c0, c6 = c0, c7 = c0;

    const int a0row = tid >> 2;
    const int a1row = a0row + 64;
    const int lk4   = (tid & 3) * 4;
    const int ga0 = brow0 + a0row;
    const int ga1 = brow0 + a1row;
    const bool av0 = (ga0 < Nrows);
    const bool av1 = (ga1 < Nrows);
    const int gb  = bcol0 + a0row;
    const float4 z4 = make_float4(0.f,0.f,0.f,0.f);

    {
        float4 va0 = av0 ? *(const float4*)&A[(long)ga0 * CDIM + lk4] : z4;
        float4 va1 = av1 ? *(const float4*)&A[(long)ga1 * CDIM + lk4] : z4;
        float4 vb  = *(const float4*)&B[(long)gb * CDIM + lk4];
        As[0][lk4 + 0][a0row] = va0.x;  As[0][lk4 + 1][a0row] = va0.y;
        As[0][lk4 + 2][a0row] = va0.z;  As[0][lk4 + 3][a0row] = va0.w;
        As[0][lk4 + 0][a1row] = va1.x;  As[0][lk4 + 1][a1row] = va1.y;
        As[0][lk4 + 2][a1row] = va1.z;  As[0][lk4 + 3][a1row] = va1.w;
        Bs[0][lk4 + 0][a0row] = vb.x;   Bs[0][lk4 + 1][a0row] = vb.y;
        Bs[0][lk4 + 2][a0row] = vb.z;   Bs[0][lk4 + 3][a0row] = vb.w;
    }
    __syncthreads();

    int buf = 0;
#pragma unroll 1
    for (int t = 0; t < CDIM / BK; t++) {
        float4 na0, na1, nb;
        const bool more = (t < CDIM / BK - 1);
        if (more) {
            int kt = (t + 1) * BK;
            na0 = av0 ? *(const float4*)&A[(long)ga0 * CDIM + kt + lk4] : z4;
            na1 = av1 ? *(const float4*)&A[(long)ga1 * CDIM + kt + lk4] : z4;
            nb  = *(const float4*)&B[(long)gb * CDIM + kt + lk4];
        }
#pragma unroll
        for (int k = 0; k < BK; k++) {
            float4 af0 = *(const float4*)&As[buf][k][ty * 8];
            float4 af1 = *(const float4*)&As[buf][k][ty * 8 + 4];
            float4 bf  = *(const float4*)&Bs[buf][k][tx * 4];
            c0.x += af0.x * bf.x; c0.y += af0.x * bf.y; c0.z += af0.x * bf.z; c0.w += af0.x * bf.w;
            c1.x += af0.y * bf.x; c1.y += af0.y * bf.y; c1.z += af0.y * bf.z; c1.w += af0.y * bf.w;
            c2.x += af0.z * bf.x; c2.y += af0.z * bf.y; c2.z += af0.z * bf.z; c2.w += af0.z * bf.w;
            c3.x += af0.w * bf.x; c3.y += af0.w * bf.y; c3.z += af0.w * bf.z; c3.w += af0.w * bf.w;
            c4.x += af1.x * bf.x; c4.y += af1.x * bf.y; c4.z += af1.x * bf.z; c4.w += af1.x * bf.w;
            c5.x += af1.y * bf.x; c5.y += af1.y * bf.y; c5.z += af1.y * bf.z; c5.w += af1.y * bf.w;
            c6.x += af1.z * bf.x; c6.y += af1.z * bf.y; c6.z += af1.z * bf.z; c6.w += af1.z * bf.w;
            c7.x += af1.w * bf.x; c7.y += af1.w * bf.y; c7.z += af1.w * bf.z; c7.w += af1.w * bf.w;
        }
        if (more) {
            int nbuf = buf ^ 1;
            As[nbuf][lk4 + 0][a0row] = na0.x;  As[nbuf][lk4 + 1][a0row] = na0.y;
            As[nbuf][lk4 + 2][a0row] = na0.z;  As[nbuf][lk4 + 3][a0row] = na0.w;
            As[nbuf][lk4 + 0][a1row] = na1.x;  As[nbuf][lk4 + 1][a1row] = na1.y;
            As[nbuf][lk4 + 2][a1row] = na1.z;  As[nbuf][lk4 + 3][a1row] = na1.w;
            Bs[nbuf][lk4 + 0][a0row] = nb.x;   Bs[nbuf][lk4 + 1][a0row] = nb.y;
            Bs[nbuf][lk4 + 2][a0row] = nb.z;   Bs[nbuf][lk4 + 3][a0row] = nb.w;
        }
        __syncthreads();
        buf ^= 1;
    }

    const int orow = brow0 + ty * 8;
    const int ocol = bcol0 + tx * 4;
    if (orow + 0 < Nrows) *(float4*)&Cmat[(long)(orow + 0) * CDIM + ocol] = c0;
    if (orow + 1 < Nrows) *(float4*)&Cmat[(long)(orow + 1) * CDIM + ocol] = c1;
    if (orow + 2 < Nrows) *(float4*)&Cmat[(long)(orow + 2) * CDIM + ocol] = c2;
    if (orow + 3 < Nrows) *(float4*)&Cmat[(long)(orow + 3) * CDIM + ocol] = c3;
    if (orow + 4 < Nrows) *(float4*)&Cmat[(long)(orow + 4) * CDIM + ocol] = c4;
    if (orow + 5 < Nrows) *(float4*)&Cmat[(long)(orow + 5) * CDIM + ocol] = c5;
    if (orow + 6 < Nrows) *(float4*)&Cmat[(long)(orow + 6) * CDIM + ocol] = c6;
    if (orow + 7 < Nrows) *(float4*)&Cmat[(long)(orow + 7) * CDIM + ocol] = c7;
}

// -------------------- edge -> vertex: sum of projected edge rows + vertex norm ----------
__global__ __launch_bounds__(CDIM4)
void vertex_gather_kernel(float4* __restrict__ out4)
{
    int v = blockIdx.x;
    int c = threadIdx.x;                 // 0..63
    int i = d_offV[v];
    int end = d_offV[v + 1];
    float dv = d_degV[v];
    float4 acc = make_float4(0.f,0.f,0.f,0.f);
    for (; i + 2 <= end; i += 2) {
        float4 p0 = d_XeP4[(long)d_csrV_e[i + 0] * CDIM4 + c];
        float4 p1 = d_XeP4[(long)d_csrV_e[i + 1] * CDIM4 + c];
        acc.x += p0.x + p1.x; acc.y += p0.y + p1.y;
        acc.z += p0.z + p1.z; acc.w += p0.w + p1.w;
    }
    for (; i < end; i++) {
        float4 p = d_XeP4[(long)d_csrV_e[i] * CDIM4 + c];
        acc.x += p.x; acc.y += p.y; acc.z += p.z; acc.w += p.w;
    }
    out4[(long)v * CDIM4 + c] = make_float4(acc.x * dv, acc.y * dv, acc.z * dv, acc.w * dv);
}

// -------------------- launch --------------------
extern "C" void kernel_launch(void* const* d_in, const int* in_sizes, int n_in,
                              void* d_out, int out_size)
{
    const float* X      = (const float*)d_in[0];
    const float* W      = (const float*)d_in[1];
    const int*   vertex = (const int*)d_in[2];
    const int*   edges  = (const int*)d_in[3];
    float* out = (float*)d_out;

    int Nv  = in_sizes[0] / CDIM;             // 20000
    int NNZ = in_sizes[2];                    // 160000
    int Me  = (int)((long)in_sizes[4] / Nv);  // 4000

    // one-time host-side resources
    static cudaStream_t s2 = nullptr;
    static cudaEvent_t evFork = nullptr, evJoin = nullptr;
    static float *pY = nullptr, *pXeP = nullptr;
    if (s2 == nullptr) {
        cudaStreamCreateWithFlags(&s2, cudaStreamNonBlocking);
        cudaEventCreateWithFlags(&evFork, cudaEventDisableTiming);
        cudaEventCreateWithFlags(&evJoin, cudaEventDisableTiming);
        cudaGetSymbolAddress((void**)&pY, d_Y4);
        cudaGetSymbolAddress((void**)&pXeP, d_XeP4);
    }

    // fork: V-prep chain on s2 (needed only by the final vertex_gather)
    cudaEventRecord(evFork, 0);
    cudaStreamWaitEvent(s2, evFork, 0);

    zeroV_kernel<<<(Nv + 255) / 256, 256, 0, s2>>>(Nv);
    countV_kernel<<<(NNZ + 255) / 256, 256, 0, s2>>>(vertex, NNZ);
    scan_kernel<<<1, 1024, 0, s2>>>(1, Nv);
    fillV_kernel<<<(NNZ + 255) / 256, 256, 0, s2>>>(vertex, edges, NNZ);
    dedupV_kernel<<<(Nv * 32 + 255) / 256, 256, 0, s2>>>(Nv);
    cudaEventRecord(evJoin, s2);

    // main stream: E-prep chain -> edge_gather(raw X) -> small GEMM
    zeroE_kernel<<<(Me + 255) / 256, 256>>>(Me);
    countE_kernel<<<(NNZ + 255) / 256, 256>>>(edges, NNZ);
    scan_kernel<<<1, 1024>>>(0, Me);
    fillE_kernel<<<(NNZ + 255) / 256, 256>>>(vertex, edges, NNZ);
    dedupE_kernel<<<(Me * 32 + 255) / 256, 256>>>(Me);

    edge_gather_kernel<<<Me, CDIM4>>>((const float4*)X);

    dim3 ggrid((Me + BM - 1) / BM, CDIM / BN);
    sgemm_kernel<<<ggrid, 256>>>(pY, W, pXeP, Me);

    // join: vertex_gather needs V-side CSR/degrees and the projected edge features
    cudaStreamWaitEvent(0, evJoin, 0);
    vertex_gather_kernel<<<Nv, CDIM4>>>((float4*)out);
}

// round 8
// speedup vs baseline: 2.8817x; 1.3165x over previous
#include <cuda_runtime.h>
#include <cuda_bf16.h>

#define CDIM   256
#define CDIM4  64          // CDIM/4
#define NV_MAX 20000
#define ME_MAX 4000
#define NNZ_MAX 160000
#define CAP_E  192         // padded CSR capacity per edge   (mean 40,  P(overflow) ~ 1e-17)
#define CAP_V  64          // padded CSR capacity per vertex (mean 8,   P(overflow) ~ 1e-35)

// -------------------- static device scratch --------------------
__device__ float4 d_Y4[ME_MAX * CDIM4];    // edge-aggregated RAW X (unscaled)   [4 MB]
__device__ float4 d_XeP4[ME_MAX * CDIM4];  // projected+scaled edge features     [4 MB]
__device__ int   d_curE[ME_MAX];           // atomic cursors == raw counts
__device__ int   d_curV[NV_MAX];
__device__ int   d_csrEp[ME_MAX * CAP_E];  // padded: vertices of edge e at [e*CAP_E ...]
__device__ int   d_csrVp[NV_MAX * CAP_V];  // padded: edges of vertex v at [v*CAP_V ...]
__device__ float d_degV[NV_MAX];           // rsqrt(distinct-edge count) or 1
__device__ float d_sE[ME_MAX];             // rsqrt(distinct-vertex cnt) / (rawcnt + 1e-8)

// -------------------- padded CSR fill, x4 ILP (no count/scan needed) --------------------
__global__ void fillE_kernel(const int4* __restrict__ vertex4, const int4* __restrict__ edges4,
                             int nnz4)
{
    int k = blockIdx.x * blockDim.x + threadIdx.x;
    if (k >= nnz4) return;
    int4 v = vertex4[k];
    int4 e = edges4[k];
    int p;
    p = atomicAdd(&d_curE[e.x], 1); if (p < CAP_E) d_csrEp[e.x * CAP_E + p] = v.x;
    p = atomicAdd(&d_curE[e.y], 1); if (p < CAP_E) d_csrEp[e.y * CAP_E + p] = v.y;
    p = atomicAdd(&d_curE[e.z], 1); if (p < CAP_E) d_csrEp[e.z * CAP_E + p] = v.z;
    p = atomicAdd(&d_curE[e.w], 1); if (p < CAP_E) d_csrEp[e.w * CAP_E + p] = v.w;
}
__global__ void fillV_kernel(const int4* __restrict__ vertex4, const int4* __restrict__ edges4,
                             int nnz4)
{
    int k = blockIdx.x * blockDim.x + threadIdx.x;
    if (k >= nnz4) return;
    int4 v = vertex4[k];
    int4 e = edges4[k];
    int q;
    q = atomicAdd(&d_curV[v.x], 1); if (q < CAP_V) d_csrVp[v.x * CAP_V + q] = e.x;
    q = atomicAdd(&d_curV[v.y], 1); if (q < CAP_V) d_csrVp[v.y * CAP_V + q] = e.y;
    q = atomicAdd(&d_curV[v.z], 1); if (q < CAP_V) d_csrVp[v.z * CAP_V + q] = e.z;
    q = atomicAdd(&d_curV[v.w], 1); if (q < CAP_V) d_csrVp[v.w * CAP_V + q] = e.w;
}

// -------------------- distinct-degree (dense-H semantics), warp per row --------------------
__global__ void dedupE_kernel(int Me)
{
    int e = (blockIdx.x * blockDim.x + threadIdx.x) >> 5;
    int lane = threadIdx.x & 31;
    if (e >= Me) return;
    int cnt = d_curE[e];
    int n = min(cnt, CAP_E);
    int base = e * CAP_E;
    int distinct = 0;
    for (int i = lane; i < n; i += 32) {
        int val = d_csrEp[base + i];
        bool dup = false;
        for (int j = 0; j < i; j++)
            if (d_csrEp[base + j] == val) { dup = true; break; }
        if (!dup) distinct++;
    }
    distinct = __reduce_add_sync(0xffffffffu, distinct);
    if (lane == 0)
        d_sE[e] = rsqrtf((float)distinct) / ((float)cnt + 1e-8f);
}
__global__ void dedupV_kernel(int Nv)
{
    int v = (blockIdx.x * blockDim.x + threadIdx.x) >> 5;
    int lane = threadIdx.x & 31;
    if (v >= Nv) return;
    int cnt = d_curV[v];
    int n = min(cnt, CAP_V);
    int base = v * CAP_V;
    int distinct = 0;
    for (int i = lane; i < n; i += 32) {
        int val = d_csrVp[base + i];
        bool dup = false;
        for (int j = 0; j < i; j++)
            if (d_csrVp[base + j] == val) { dup = true; break; }
        if (!dup) distinct++;
    }
    distinct = __reduce_add_sync(0xffffffffu, distinct);
    if (lane == 0)
        d_degV[v] = (distinct == 0) ? 1.0f : rsqrtf((float)distinct);
}

// -------------------- vertex -> edge on RAW X: plain sum (scale folded into GEMM) --------
__global__ __launch_bounds__(CDIM4)
void edge_gather_kernel(const float4* __restrict__ X4)
{
    int e = blockIdx.x;
    int c = threadIdx.x;                 // 0..63
    int n = min(d_curE[e], CAP_E);
    int base = e * CAP_E;
    float4 acc = make_float4(0.f,0.f,0.f,0.f);
    int i = 0;
    for (; i + 4 <= n; i += 4) {
        float4 p0 = X4[(long)d_csrEp[base + i + 0] * CDIM4 + c];
        float4 p1 = X4[(long)d_csrEp[base + i + 1] * CDIM4 + c];
        float4 p2 = X4[(long)d_csrEp[base + i + 2] * CDIM4 + c];
        float4 p3 = X4[(long)d_csrEp[base + i + 3] * CDIM4 + c];
        acc.x += (p0.x + p1.x) + (p2.x + p3.x);
        acc.y += (p0.y + p1.y) + (p2.y + p3.y);
        acc.z += (p0.z + p1.z) + (p2.z + p3.z);
        acc.w += (p0.w + p1.w) + (p2.w + p3.w);
    }
    for (; i < n; i++) {
        float4 p = X4[(long)d_csrEp[base + i] * CDIM4 + c];
        acc.x += p.x; acc.y += p.y; acc.z += p.z; acc.w += p.w;
    }
    d_Y4[(long)e * CDIM4 + c] = acc;
}

// -------------------- SGEMM: XeP = (Y @ W^T) * sE[row]  (M=4000, K=256) ------------------
#define BM 128
#define BN 64
#define BK 16

__global__ __launch_bounds__(256)
void sgemm_kernel(const float* __restrict__ A, const float* __restrict__ B,
                  float* __restrict__ Cmat, int Nrows)
{
    __shared__ float As[2][BK][BM];
    __shared__ float Bs[2][BK][BN];

    const int tid = threadIdx.x;
    const int brow0 = blockIdx.x * BM;
    const int bcol0 = blockIdx.y * BN;
    const int tx = tid & 15;
    const int ty = tid >> 4;

    float4 c0 = make_float4(0.f,0.f,0.f,0.f);
    float4 c1 = c0, c2 = c0, c3 = c0, c4 = c0, c5 = c0, c6 = c0, c7 = c0;

    const int a0row = tid >> 2;
    const int a1row = a0row + 64;
    const int lk4   = (tid & 3) * 4;
    const int ga0 = brow0 + a0row;
    const int ga1 = brow0 + a1row;
    const bool av0 = (ga0 < Nrows);
    const bool av1 = (ga1 < Nrows);
    const int gb  = bcol0 + a0row;
    const float4 z4 = make_float4(0.f,0.f,0.f,0.f);

    {
        float4 va0 = av0 ? *(const float4*)&A[(long)ga0 * CDIM + lk4] : z4;
        float4 va1 = av1 ? *(const float4*)&A[(long)ga1 * CDIM + lk4] : z4;
        float4 vb  = *(const float4*)&B[(long)gb * CDIM + lk4];
        As[0][lk4 + 0][a0row] = va0.x;  As[0][lk4 + 1][a0row] = va0.y;
        As[0][lk4 + 2][a0row] = va0.z;  As[0][lk4 + 3][a0row] = va0.w;
        As[0][lk4 + 0][a1row] = va1.x;  As[0][lk4 + 1][a1row] = va1.y;
        As[0][lk4 + 2][a1row] = va1.z;  As[0][lk4 + 3][a1row] = va1.w;
        Bs[0][lk4 + 0][a0row] = vb.x;   Bs[0][lk4 + 1][a0row] = vb.y;
        Bs[0][lk4 + 2][a0row] = vb.z;   Bs[0][lk4 + 3][a0row] = vb.w;
    }
    __syncthreads();

    int buf = 0;
#pragma unroll 1
    for (int t = 0; t < CDIM / BK; t++) {
        float4 na0, na1, nb;
        const bool more = (t < CDIM / BK - 1);
        if (more) {
            int kt = (t + 1) * BK;
            na0 = av0 ? *(const float4*)&A[(long)ga0 * CDIM + kt + lk4] : z4;
            na1 = av1 ? *(const float4*)&A[(long)ga1 * CDIM + kt + lk4] : z4;
            nb  = *(const float4*)&B[(long)gb * CDIM + kt + lk4];
        }
#pragma unroll
        for (int k = 0; k < BK; k++) {
            float4 af0 = *(const float4*)&As[buf][k][ty * 8];
            float4 af1 = *(const float4*)&As[buf][k][ty * 8 + 4];
            float4 bf  = *(const float4*)&Bs[buf][k][tx * 4];
            c0.x += af0.x * bf.x; c0.y += af0.x * bf.y; c0.z += af0.x * bf.z; c0.w += af0.x * bf.w;
            c1.x += af0.y * bf.x; c1.y += af0.y * bf.y; c1.z += af0.y * bf.z; c1.w += af0.y * bf.w;
            c2.x += af0.z * bf.x; c2.y += af0.z * bf.y; c2.z += af0.z * bf.z; c2.w += af0.z * bf.w;
            c3.x += af0.w * bf.x; c3.y += af0.w * bf.y; c3.z += af0.w * bf.z; c3.w += af0.w * bf.w;
            c4.x += af1.x * bf.x; c4.y += af1.x * bf.y; c4.z += af1.x * bf.z; c4.w += af1.x * bf.w;
            c5.x += af1.y * bf.x; c5.y += af1.y * bf.y; c5.z += af1.y * bf.z; c5.w += af1.y * bf.w;
            c6.x += af1.z * bf.x; c6.y += af1.z * bf.y; c6.z += af1.z * bf.z; c6.w += af1.z * bf.w;
            c7.x += af1.w * bf.x; c7.y += af1.w * bf.y; c7.z += af1.w * bf.z; c7.w += af1.w * bf.w;
        }
        if (more) {
            int nbuf = buf ^ 1;
            As[nbuf][lk4 + 0][a0row] = na0.x;  As[nbuf][lk4 + 1][a0row] = na0.y;
            As[nbuf][lk4 + 2][a0row] = na0.z;  As[nbuf][lk4 + 3][a0row] = na0.w;
            As[nbuf][lk4 + 0][a1row] = na1.x;  As[nbuf][lk4 + 1][a1row] = na1.y;
            As[nbuf][lk4 + 2][a1row] = na1.z;  As[nbuf][lk4 + 3][a1row] = na1.w;
            Bs[nbuf][lk4 + 0][a0row] = nb.x;   Bs[nbuf][lk4 + 1][a0row] = nb.y;
            Bs[nbuf][lk4 + 2][a0row] = nb.z;   Bs[nbuf][lk4 + 3][a0row] = nb.w;
        }
        __syncthreads();
        buf ^= 1;
    }

    const int orow = brow0 + ty * 8;
    const int ocol = bcol0 + tx * 4;
    // fold edge scale sE into the epilogue (row scale)
    if (orow + 0 < Nrows) { float s = d_sE[orow + 0];
        *(float4*)&Cmat[(long)(orow + 0) * CDIM + ocol] = make_float4(c0.x*s, c0.y*s, c0.z*s, c0.w*s); }
    if (orow + 1 < Nrows) { float s = d_sE[orow + 1];
        *(float4*)&Cmat[(long)(orow + 1) * CDIM + ocol] = make_float4(c1.x*s, c1.y*s, c1.z*s, c1.w*s); }
    if (orow + 2 < Nrows) { float s = d_sE[orow + 2];
        *(float4*)&Cmat[(long)(orow + 2) * CDIM + ocol] = make_float4(c2.x*s, c2.y*s, c2.z*s, c2.w*s); }
    if (orow + 3 < Nrows) { float s = d_sE[orow + 3];
        *(float4*)&Cmat[(long)(orow + 3) * CDIM + ocol] = make_float4(c3.x*s, c3.y*s, c3.z*s, c3.w*s); }
    if (orow + 4 < Nrows) { float s = d_sE[orow + 4];
        *(float4*)&Cmat[(long)(orow + 4) * CDIM + ocol] = make_float4(c4.x*s, c4.y*s, c4.z*s, c4.w*s); }
    if (orow + 5 < Nrows) { float s = d_sE[orow + 5];
        *(float4*)&Cmat[(long)(orow + 5) * CDIM + ocol] = make_float4(c5.x*s, c5.y*s, c5.z*s, c5.w*s); }
    if (orow + 6 < Nrows) { float s = d_sE[orow + 6];
        *(float4*)&Cmat[(long)(orow + 6) * CDIM + ocol] = make_float4(c6.x*s, c6.y*s, c6.z*s, c6.w*s); }
    if (orow + 7 < Nrows) { float s = d_sE[orow + 7];
        *(float4*)&Cmat[(long)(orow + 7) * CDIM + ocol] = make_float4(c7.x*s, c7.y*s, c7.z*s, c7.w*s); }
}

// -------------------- edge -> vertex: sum of projected edge rows + vertex norm ----------
__global__ __launch_bounds__(CDIM4)
void vertex_gather_kernel(float4* __restrict__ out4)
{
    int v = blockIdx.x;
    int c = threadIdx.x;                 // 0..63
    int n = min(d_curV[v], CAP_V);
    int base = v * CAP_V;
    float dv = d_degV[v];
    float4 acc = make_float4(0.f,0.f,0.f,0.f);
    int i = 0;
    for (; i + 4 <= n; i += 4) {
        float4 p0 = d_XeP4[(long)d_csrVp[base + i + 0] * CDIM4 + c];
        float4 p1 = d_XeP4[(long)d_csrVp[base + i + 1] * CDIM4 + c];
        float4 p2 = d_XeP4[(long)d_csrVp[base + i + 2] * CDIM4 + c];
        float4 p3 = d_XeP4[(long)d_csrVp[base + i + 3] * CDIM4 + c];
        acc.x += (p0.x + p1.x) + (p2.x + p3.x);
        acc.y += (p0.y + p1.y) + (p2.y + p3.y);
        acc.z += (p0.z + p1.z) + (p2.z + p3.z);
        acc.w += (p0.w + p1.w) + (p2.w + p3.w);
    }
    for (; i < n; i++) {
        float4 p = d_XeP4[(long)d_csrVp[base + i] * CDIM4 + c];
        acc.x += p.x; acc.y += p.y; acc.z += p.z; acc.w += p.w;
    }
    out4[(long)v * CDIM4 + c] = make_float4(acc.x * dv, acc.y * dv, acc.z * dv, acc.w * dv);
}

// -------------------- launch --------------------
extern "C" void kernel_launch(void* const* d_in, const int* in_sizes, int n_in,
                              void* d_out, int out_size)
{
    const float* X      = (const float*)d_in[0];
    const float* W      = (const float*)d_in[1];
    const int*   vertex = (const int*)d_in[2];
    const int*   edges  = (const int*)d_in[3];
    float* out = (float*)d_out;

    int Nv  = in_sizes[0] / CDIM;             // 20000
    int NNZ = in_sizes[2];                    // 160000
    int Me  = (int)((long)in_sizes[4] / Nv);  // 4000
    int nnz4 = NNZ / 4;                       // NNZ divisible by 4 (160000)

    // one-time host-side resources (no device allocations)
    static cudaStream_t s2 = nullptr, s3 = nullptr;
    static cudaEvent_t evFork = nullptr, evFillE = nullptr, evSE = nullptr, evJoinV = nullptr;
    static float *pY = nullptr, *pXeP = nullptr;
    static int *pCurE = nullptr, *pCurV = nullptr;
    if (s2 == nullptr) {
        cudaStreamCreateWithFlags(&s2, cudaStreamNonBlocking);
        cudaStreamCreateWithFlags(&s3, cudaStreamNonBlocking);
        cudaEventCreateWithFlags(&evFork,  cudaEventDisableTiming);
        cudaEventCreateWithFlags(&evFillE, cudaEventDisableTiming);
        cudaEventCreateWithFlags(&evSE,    cudaEventDisableTiming);
        cudaEventCreateWithFlags(&evJoinV, cudaEventDisableTiming);
        cudaGetSymbolAddress((void**)&pY,    d_Y4);
        cudaGetSymbolAddress((void**)&pXeP,  d_XeP4);
        cudaGetSymbolAddress((void**)&pCurE, d_curE);
        cudaGetSymbolAddress((void**)&pCurV, d_curV);
    }

    // fork for the V-chain
    cudaEventRecord(evFork, 0);
    cudaStreamWaitEvent(s2, evFork, 0);

    // V-chain (only needed by final vertex_gather): zero cursors -> fill -> dedup
    cudaMemsetAsync(pCurV, 0, (size_t)Nv * sizeof(int), s2);
    fillV_kernel<<<(nnz4 + 255) / 256, 256, 0, s2>>>((const int4*)vertex, (const int4*)edges, nnz4);
    dedupV_kernel<<<(Nv * 32 + 255) / 256, 256, 0, s2>>>(Nv);
    cudaEventRecord(evJoinV, s2);

    // main: E-chain -> edge_gather -> GEMM
    cudaMemsetAsync(pCurE, 0, (size_t)Me * sizeof(int), 0);
    fillE_kernel<<<(nnz4 + 255) / 256, 256>>>((const int4*)vertex, (const int4*)edges, nnz4);
    cudaEventRecord(evFillE, 0);

    // dedupE runs concurrently with edge_gather on s3 (GEMM consumes sE in its epilogue)
    cudaStreamWaitEvent(s3, evFillE, 0);
    dedupE_kernel<<<(Me * 32 + 255) / 256, 256, 0, s3>>>(Me);
    cudaEventRecord(evSE, s3);

    edge_gather_kernel<<<Me, CDIM4>>>((const float4*)X);

    cudaStreamWaitEvent(0, evSE, 0);
    dim3 ggrid((Me + BM - 1) / BM, CDIM / BN);
    sgemm_kernel<<<ggrid, 256>>>(pY, W, pXeP, Me);

    cudaStreamWaitEvent(0, evJoinV, 0);
    vertex_gather_kernel<<<Nv, CDIM4>>>((float4*)out);
}